// round 5
// baseline (speedup 1.0000x reference)
#include <cuda_runtime.h>
#include <cstdint>

#define NN 50000
#define EE 800000
#define SCAN_BLOCKS 49

typedef unsigned long long u64;

// Scratch (device globals; no dynamic allocation allowed)
__device__ float g_h1[(size_t)NN * 128];   // W1 @ nfeat + b_ne per node
__device__ float g_WcT[32 * 128];          // (W2 @ W_edge)T: [c][j]
__device__ u64   g_W1d[128 * 128];         // dup'd {w,w} W1T: [k][j]
__device__ u64   g_Wsd[128 * 128];         // dup'd {w,w} W_selfT: [k][j]
__device__ int   g_deg[NN];
__device__ int   g_incl[NN];
__device__ int   g_cursor[NN];
__device__ int   g_bsum[64];
__device__ int   g_bpre[64];
__device__ int   g_eperm[EE];              // edge ids grouped by dst
__device__ int   g_esrc[EE];               // src ids grouped by dst
__device__ int   g_edst[EE];               // dst ids grouped by dst (sorted-ish)
__device__ int   g_neigh[(size_t)NN * 128]; // float bits, atomicMax accumulator

// ---------------- packed fp32x2 helpers (exact fp32 semantics) ----------------
__device__ __forceinline__ u64 pk2(float a, float b) {
    u64 r; asm("mov.b64 %0, {%1, %2};" : "=l"(r) : "f"(a), "f"(b)); return r;
}
__device__ __forceinline__ void fma2(u64& d, u64 a, u64 b) {
    asm("fma.rn.f32x2 %0, %1, %2, %0;" : "+l"(d) : "l"(a), "l"(b));
}
__device__ __forceinline__ float2 up2(u64 v) {
    float2 f; asm("mov.b64 {%0, %1}, %2;" : "=f"(f.x), "=f"(f.y) : "l"(v)); return f;
}

// ---------------- prep: Wc = W2 @ W_edge, stored transposed ----------------
__global__ void k_wc(const float* __restrict__ W_ne, const float* __restrict__ W_edge) {
    int c = blockIdx.x;    // 0..31
    int o = threadIdx.x;   // 0..127
    float s = 0.f;
    #pragma unroll 8
    for (int j = 0; j < 128; j++)
        s += W_ne[o * 256 + 128 + j] * W_edge[j * 32 + c];
    g_WcT[c * 128 + o] = s;
}

// ---------------- prep: duplicated-transposed W1 / W_self; zero deg ----------------
__global__ void k_prep(const float* __restrict__ W_ne, const float* __restrict__ W_self) {
    int idx = blockIdx.x * blockDim.x + threadIdx.x;  // 16384
    int j = idx >> 7, k = idx & 127;
    float w1 = W_ne[j * 256 + k];
    float ws = W_self[j * 128 + k];
    g_W1d[k * 128 + j] = pk2(w1, w1);
    g_Wsd[k * 128 + j] = pk2(ws, ws);
    for (int n = idx; n < NN; n += 16384) g_deg[n] = 0;
}

// ---------------- zero the neigh accumulator ----------------
__global__ void k_zero() {
    int idx = blockIdx.x * blockDim.x + threadIdx.x;  // NN*128/4 = 1.6M
    int4 z = {0, 0, 0, 0};
    ((int4*)g_neigh)[idx] = z;
}

// ---------------- degree count ----------------
__global__ void k_count(const int* __restrict__ dst) {
    int e = blockIdx.x * blockDim.x + threadIdx.x;
    if (e < EE) atomicAdd(&g_deg[dst[e]], 1);
}

// ---------------- scan A: per-block inclusive scan ----------------
__global__ void k_scanA() {
    int n = blockIdx.x * 1024 + threadIdx.x;
    int lane = threadIdx.x & 31, w = threadIdx.x >> 5;
    int v = (n < NN) ? g_deg[n] : 0;
    int x = v;
    #pragma unroll
    for (int d = 1; d < 32; d <<= 1) {
        int y = __shfl_up_sync(0xffffffffu, x, d);
        if (lane >= d) x += y;
    }
    __shared__ int ws[32];
    if (lane == 31) ws[w] = x;
    __syncthreads();
    if (w == 0) {
        int y = ws[lane];
        #pragma unroll
        for (int d = 1; d < 32; d <<= 1) {
            int z = __shfl_up_sync(0xffffffffu, y, d);
            if (lane >= d) y += z;
        }
        ws[lane] = y;
    }
    __syncthreads();
    int incl = x + ((w > 0) ? ws[w - 1] : 0);
    if (n < NN) g_incl[n] = incl;
    if (threadIdx.x == 1023) g_bsum[blockIdx.x] = incl;
}

// ---------------- scan B: block sums ----------------
__global__ void k_scanB() {
    __shared__ int s[64];
    int t = threadIdx.x;
    int v = (t < SCAN_BLOCKS) ? g_bsum[t] : 0;
    s[t] = v;
    __syncthreads();
    for (int d = 1; d < 64; d <<= 1) {
        int y = (t >= d) ? s[t - d] : 0;
        __syncthreads();
        s[t] += y;
        __syncthreads();
    }
    if (t < SCAN_BLOCKS) g_bpre[t] = s[t] - v;
}

// ---------------- scan C: cursors ----------------
__global__ void k_scanC() {
    int n = blockIdx.x * 1024 + threadIdx.x;
    if (n < NN)
        g_cursor[n] = g_incl[n] - g_deg[n] + g_bpre[blockIdx.x];
}

// ---------------- scatter: edge id + src + dst into dst-grouped order ----------------
__global__ void k_scatter(const int* __restrict__ dst, const int* __restrict__ src) {
    int e = blockIdx.x * blockDim.x + threadIdx.x;
    if (e < EE) {
        int d = dst[e];
        int s = src[e];
        int p = atomicAdd(&g_cursor[d], 1);
        g_eperm[p] = e;
        g_esrc[p] = s;
        g_edst[p] = d;
    }
}

// ---------------- node GEMM: 8 nodes/warp, node-pair f32x2, dup'd weights ----------------
__global__ void __launch_bounds__(256) k_node(const float* __restrict__ nfeat,
                       const float* __restrict__ b_ne,
                       const float* __restrict__ b_self,
                       float* __restrict__ out_self) {
    __shared__ float sX[8][1024];  // per-warp: [k*8 + n], natural node pairs
    int lane = threadIdx.x & 31, wip = threadIdx.x >> 5;
    int warp = blockIdx.x * 8 + wip;
    if (warp >= NN / 8) return;    // 6250 warps exactly
    int n0 = warp * 8;
    float* sx = sX[wip];

    // stage x transposed: lane loads node kq = lane>>2, dims (lane&3)*32..+31
    int kq = lane >> 2;
    int db = (lane & 3) * 32;
    const float4* xr = (const float4*)(nfeat + (size_t)(n0 + kq) * 128 + db);
    #pragma unroll
    for (int i = 0; i < 8; i++) {
        float4 v = xr[i];
        sx[(db + i * 4 + 0) * 8 + kq] = v.x;
        sx[(db + i * 4 + 1) * 8 + kq] = v.y;
        sx[(db + i * 4 + 2) * 8 + kq] = v.z;
        sx[(db + i * 4 + 3) * 8 + kq] = v.w;
    }
    __syncwarp();

    int j4 = lane * 4;
    u64 ah[4][4], as[4][4];  // [node pair p][jj]
    #pragma unroll
    for (int p = 0; p < 4; p++)
        #pragma unroll
        for (int jj = 0; jj < 4; jj++) { ah[p][jj] = 0ull; as[p][jj] = 0ull; }

    #pragma unroll 8
    for (int k = 0; k < 128; k++) {
        u64 w10 = g_W1d[k * 128 + j4 + 0], w11 = g_W1d[k * 128 + j4 + 1];
        u64 w12 = g_W1d[k * 128 + j4 + 2], w13 = g_W1d[k * 128 + j4 + 3];
        u64 ws0 = g_Wsd[k * 128 + j4 + 0], ws1 = g_Wsd[k * 128 + j4 + 1];
        u64 ws2 = g_Wsd[k * 128 + j4 + 2], ws3 = g_Wsd[k * 128 + j4 + 3];
        const u64* xp = (const u64*)(sx + k * 8);
        #pragma unroll
        for (int p = 0; p < 4; p++) {
            u64 x2 = xp[p];  // {x_{n0+2p}[k], x_{n0+2p+1}[k]} broadcast LDS.64
            fma2(ah[p][0], w10, x2); fma2(ah[p][1], w11, x2);
            fma2(ah[p][2], w12, x2); fma2(ah[p][3], w13, x2);
            fma2(as[p][0], ws0, x2); fma2(as[p][1], ws1, x2);
            fma2(as[p][2], ws2, x2); fma2(as[p][3], ws3, x2);
        }
    }

    float4 bh = *(const float4*)&b_ne[j4];
    float4 bs = *(const float4*)&b_self[j4];
    #pragma unroll
    for (int p = 0; p < 4; p++) {
        float2 f0 = up2(ah[p][0]), f1 = up2(ah[p][1]), f2 = up2(ah[p][2]), f3 = up2(ah[p][3]);
        float2 g0 = up2(as[p][0]), g1 = up2(as[p][1]), g2 = up2(as[p][2]), g3 = up2(as[p][3]);
        size_t ra = (size_t)(n0 + 2 * p) * 128 + j4;
        size_t rb = (size_t)(n0 + 2 * p + 1) * 128 + j4;
        *(float4*)&g_h1[ra] = make_float4(f0.x + bh.x, f1.x + bh.y, f2.x + bh.z, f3.x + bh.w);
        *(float4*)&g_h1[rb] = make_float4(f0.y + bh.x, f1.y + bh.y, f2.y + bh.z, f3.y + bh.w);
        *(float4*)&out_self[ra] = make_float4(g0.x + bs.x, g1.x + bs.y, g2.x + bs.z, g3.x + bs.w);
        *(float4*)&out_self[rb] = make_float4(g0.y + bs.x, g1.y + bs.y, g2.y + bs.z, g3.y + bs.w);
    }
}

// ---------------- edge kernel: flat 16-edge tiles, zero padding, segmented max + atomics ----------------
__device__ __forceinline__ void flushmax(int d, int j4, float c0, float c1, float c2, float c3) {
    int* np = &g_neigh[(size_t)d * 128 + j4];
    atomicMax(np + 0, __float_as_int(c0));
    atomicMax(np + 1, __float_as_int(c1));
    atomicMax(np + 2, __float_as_int(c2));
    atomicMax(np + 3, __float_as_int(c3));
}

__global__ void __launch_bounds__(256) k_edge(const float* __restrict__ etype) {
    __shared__ float sW[32 * 128];   // 16 KB: [c][j]
    __shared__ float sE[8][512];     // per-warp transposed etype tile: [c*16 + k]
    for (int i = threadIdx.x; i < 32 * 128; i += 256)
        sW[i] = g_WcT[i];
    __syncthreads();

    int lane = threadIdx.x & 31;
    int wip = threadIdx.x >> 5;
    int tile = blockIdx.x * 8 + wip;   // 6250 blocks * 8 = 50000 tiles, EE/16 exact
    int base = tile * 16;
    int j4 = lane * 4;
    float* sEw = sE[wip];

    int e_l = 0, s_l = 0, d_l = 0;
    if (lane < 16) {
        e_l = g_eperm[base + lane];
        s_l = g_esrc[base + lane];
        d_l = g_edst[base + lane];
    }

    // stage etype transposed: lane handles edge slot kq, column half cb
    int kq = lane >> 1, cb = (lane & 1) * 16;
    int ek = __shfl_sync(0xffffffffu, e_l, kq);
    {
        const float4* er = (const float4*)(etype + (size_t)ek * 32 + cb);
        float4 a = er[0], b = er[1], c = er[2], d = er[3];
        sEw[(cb + 0) * 16 + kq] = a.x;  sEw[(cb + 1) * 16 + kq] = a.y;
        sEw[(cb + 2) * 16 + kq] = a.z;  sEw[(cb + 3) * 16 + kq] = a.w;
        sEw[(cb + 4) * 16 + kq] = b.x;  sEw[(cb + 5) * 16 + kq] = b.y;
        sEw[(cb + 6) * 16 + kq] = b.z;  sEw[(cb + 7) * 16 + kq] = b.w;
        sEw[(cb + 8) * 16 + kq] = c.x;  sEw[(cb + 9) * 16 + kq] = c.y;
        sEw[(cb + 10) * 16 + kq] = c.z; sEw[(cb + 11) * 16 + kq] = c.w;
        sEw[(cb + 12) * 16 + kq] = d.x; sEw[(cb + 13) * 16 + kq] = d.y;
        sEw[(cb + 14) * 16 + kq] = d.z; sEw[(cb + 15) * 16 + kq] = d.w;
    }

    // init acc pairs with gathered h1
    u64 acc[8][4];
    #pragma unroll
    for (int p = 0; p < 8; p++) {
        int s0 = __shfl_sync(0xffffffffu, s_l, 2 * p);
        int s1 = __shfl_sync(0xffffffffu, s_l, 2 * p + 1);
        float4 h0 = *(const float4*)&g_h1[(size_t)s0 * 128 + j4];
        float4 h1 = *(const float4*)&g_h1[(size_t)s1 * 128 + j4];
        acc[p][0] = pk2(h0.x, h1.x); acc[p][1] = pk2(h0.y, h1.y);
        acc[p][2] = pk2(h0.z, h1.z); acc[p][3] = pk2(h0.w, h1.w);
    }
    __syncwarp();

    #pragma unroll
    for (int c = 0; c < 32; c++) {
        float4 w = *(const float4*)&sW[c * 128 + j4];
        u64 w0 = pk2(w.x, w.x), w1 = pk2(w.y, w.y);
        u64 w2 = pk2(w.z, w.z), w3 = pk2(w.w, w.w);
        const u64* ep = (const u64*)(sEw + c * 16);
        #pragma unroll
        for (int p = 0; p < 8; p++) {
            u64 ce = ep[p];   // {e_{2p}[c], e_{2p+1}[c]} broadcast LDS.64
            fma2(acc[p][0], w0, ce);
            fma2(acc[p][1], w1, ce);
            fma2(acc[p][2], w2, ce);
            fma2(acc[p][3], w3, ce);
        }
    }

    // register segmented max over the 16 CSR-ordered edges, flush at dst changes.
    // running max starts at 0 => relu absorbed; atomicMax(int) exact for floats >= 0.
    float c0 = 0.f, c1 = 0.f, c2 = 0.f, c3 = 0.f;
    int dprev = __shfl_sync(0xffffffffu, d_l, 0);
    #pragma unroll
    for (int p = 0; p < 8; p++) {
        float2 f0 = up2(acc[p][0]), f1 = up2(acc[p][1]);
        float2 f2 = up2(acc[p][2]), f3 = up2(acc[p][3]);
        int da = __shfl_sync(0xffffffffu, d_l, 2 * p);
        int db = __shfl_sync(0xffffffffu, d_l, 2 * p + 1);
        if (da != dprev) {
            flushmax(dprev, j4, c0, c1, c2, c3);
            c0 = c1 = c2 = c3 = 0.f;
        }
        c0 = fmaxf(c0, f0.x); c1 = fmaxf(c1, f1.x);
        c2 = fmaxf(c2, f2.x); c3 = fmaxf(c3, f3.x);
        if (db != da) {
            flushmax(da, j4, c0, c1, c2, c3);
            c0 = c1 = c2 = c3 = 0.f;
        }
        c0 = fmaxf(c0, f0.y); c1 = fmaxf(c1, f1.y);
        c2 = fmaxf(c2, f2.y); c3 = fmaxf(c3, f3.y);
        dprev = db;
    }
    flushmax(dprev, j4, c0, c1, c2, c3);
}

// ---------------- final: out = self + (1+eps)*neigh ----------------
__global__ void k_final(const float* __restrict__ eps, float* __restrict__ out) {
    float s = 1.0f + eps[0];
    int idx = blockIdx.x * blockDim.x + threadIdx.x;  // NN*128/4
    float4 o = ((float4*)out)[idx];
    int4 nb = ((const int4*)g_neigh)[idx];
    o.x = fmaf(s, __int_as_float(nb.x), o.x);
    o.y = fmaf(s, __int_as_float(nb.y), o.y);
    o.z = fmaf(s, __int_as_float(nb.z), o.z);
    o.w = fmaf(s, __int_as_float(nb.w), o.w);
    ((float4*)out)[idx] = o;
}

extern "C" void kernel_launch(void* const* d_in, const int* in_sizes, int n_in,
                              void* d_out, int out_size) {
    const float* nfeat  = (const float*)d_in[0];
    const float* etype  = (const float*)d_in[1];
    const int*   src    = (const int*)d_in[2];
    const int*   dst    = (const int*)d_in[3];
    const float* W_edge = (const float*)d_in[4];
    const float* W_ne   = (const float*)d_in[5];
    const float* b_ne   = (const float*)d_in[6];
    const float* W_self = (const float*)d_in[7];
    const float* b_self = (const float*)d_in[8];
    const float* eps    = (const float*)d_in[9];
    float* out = (float*)d_out;

    k_wc<<<32, 128>>>(W_ne, W_edge);
    k_prep<<<64, 256>>>(W_ne, W_self);
    k_zero<<<(NN * 128 / 4) / 256, 256>>>();
    k_count<<<(EE + 255) / 256, 256>>>(dst);
    k_scanA<<<SCAN_BLOCKS, 1024>>>();
    k_scanB<<<1, 64>>>();
    k_scanC<<<SCAN_BLOCKS, 1024>>>();
    k_scatter<<<(EE + 255) / 256, 256>>>(dst, src);
    k_node<<<(NN / 8 + 7) / 8, 256>>>(nfeat, b_ne, b_self, out);
    k_edge<<<EE / 16 / 8, 256>>>(etype);
    k_final<<<(NN * 128 / 4) / 256, 256>>>(eps, out);
}

// round 6
// speedup vs baseline: 1.0514x; 1.0514x over previous
#include <cuda_runtime.h>
#include <cstdint>

#define NN 50000
#define EE 800000
#define SCAN_BLOCKS 49

typedef unsigned long long u64;

// Scratch (device globals; no dynamic allocation allowed)
__device__ float g_h1[(size_t)NN * 128];   // W1 @ nfeat + b_ne per node (exact fp32)
__device__ float g_WcT[32 * 128];          // (W2 @ W_edge)T, tf32-rounded: [c][j]
__device__ float g_W1T[128 * 128];         // W1T: [k][j]
__device__ float g_WsT[128 * 128];         // W_selfT: [k][j]
__device__ int   g_deg[NN];
__device__ int   g_incl[NN];
__device__ int   g_cursor[NN];
__device__ int   g_bsum[64];
__device__ int   g_bpre[64];
__device__ int   g_eperm[EE];              // edge ids grouped by dst
__device__ int   g_esrc[EE];               // src ids grouped by dst
__device__ int   g_edst[EE];               // dst ids grouped by dst (non-decreasing)
__device__ int   g_neigh[(size_t)NN * 128]; // float bits, atomicMax accumulator

// ---------------- helpers ----------------
__device__ __forceinline__ u64 pk2(float a, float b) {
    u64 r; asm("mov.b64 %0, {%1, %2};" : "=l"(r) : "f"(a), "f"(b)); return r;
}
__device__ __forceinline__ void fma2(u64& d, u64 a, u64 b) {
    asm("fma.rn.f32x2 %0, %1, %2, %0;" : "+l"(d) : "l"(a), "l"(b));
}
__device__ __forceinline__ float2 up2(u64 v) {
    float2 f; asm("mov.b64 {%0, %1}, %2;" : "=f"(f.x), "=f"(f.y) : "l"(v)); return f;
}
__device__ __forceinline__ unsigned tf32r(float x) {
    unsigned r; asm("cvt.rna.tf32.f32 %0, %1;" : "=r"(r) : "f"(x)); return r;
}
__device__ __forceinline__ void mma_tf32(float& c0, float& c1, float& c2, float& c3,
                                         unsigned a0, unsigned a1, unsigned a2, unsigned a3,
                                         unsigned b0, unsigned b1) {
    asm("mma.sync.aligned.m16n8k8.row.col.f32.tf32.tf32.f32 "
        "{%0,%1,%2,%3}, {%4,%5,%6,%7}, {%8,%9}, {%0,%1,%2,%3};"
        : "+f"(c0), "+f"(c1), "+f"(c2), "+f"(c3)
        : "r"(a0), "r"(a1), "r"(a2), "r"(a3), "r"(b0), "r"(b1));
}

// ---------------- prep: Wc = W2 @ W_edge, transposed, tf32-rounded ----------------
__global__ void k_wc(const float* __restrict__ W_ne, const float* __restrict__ W_edge) {
    int c = blockIdx.x;    // 0..31
    int o = threadIdx.x;   // 0..127
    float s = 0.f;
    #pragma unroll 8
    for (int j = 0; j < 128; j++)
        s += W_ne[o * 256 + 128 + j] * W_edge[j * 32 + c];
    g_WcT[c * 128 + o] = __uint_as_float(tf32r(s));
}

// ---------------- prep: transpose W1 / W_self; zero deg ----------------
__global__ void k_prep(const float* __restrict__ W_ne, const float* __restrict__ W_self) {
    int idx = blockIdx.x * blockDim.x + threadIdx.x;  // 16384
    int j = idx >> 7, k = idx & 127;
    g_W1T[k * 128 + j] = W_ne[j * 256 + k];
    g_WsT[k * 128 + j] = W_self[j * 128 + k];
    for (int n = idx; n < NN; n += 16384) g_deg[n] = 0;
}

// ---------------- zero the neigh accumulator ----------------
__global__ void k_zero() {
    int idx = blockIdx.x * blockDim.x + threadIdx.x;  // NN*128/4
    int4 z = {0, 0, 0, 0};
    ((int4*)g_neigh)[idx] = z;
}

// ---------------- degree count ----------------
__global__ void k_count(const int* __restrict__ dst) {
    int e = blockIdx.x * blockDim.x + threadIdx.x;
    if (e < EE) atomicAdd(&g_deg[dst[e]], 1);
}

// ---------------- scan A ----------------
__global__ void k_scanA() {
    int n = blockIdx.x * 1024 + threadIdx.x;
    int lane = threadIdx.x & 31, w = threadIdx.x >> 5;
    int v = (n < NN) ? g_deg[n] : 0;
    int x = v;
    #pragma unroll
    for (int d = 1; d < 32; d <<= 1) {
        int y = __shfl_up_sync(0xffffffffu, x, d);
        if (lane >= d) x += y;
    }
    __shared__ int ws[32];
    if (lane == 31) ws[w] = x;
    __syncthreads();
    if (w == 0) {
        int y = ws[lane];
        #pragma unroll
        for (int d = 1; d < 32; d <<= 1) {
            int z = __shfl_up_sync(0xffffffffu, y, d);
            if (lane >= d) y += z;
        }
        ws[lane] = y;
    }
    __syncthreads();
    int incl = x + ((w > 0) ? ws[w - 1] : 0);
    if (n < NN) g_incl[n] = incl;
    if (threadIdx.x == 1023) g_bsum[blockIdx.x] = incl;
}

// ---------------- scan B ----------------
__global__ void k_scanB() {
    __shared__ int s[64];
    int t = threadIdx.x;
    int v = (t < SCAN_BLOCKS) ? g_bsum[t] : 0;
    s[t] = v;
    __syncthreads();
    for (int d = 1; d < 64; d <<= 1) {
        int y = (t >= d) ? s[t - d] : 0;
        __syncthreads();
        s[t] += y;
        __syncthreads();
    }
    if (t < SCAN_BLOCKS) g_bpre[t] = s[t] - v;
}

// ---------------- scan C: cursors ----------------
__global__ void k_scanC() {
    int n = blockIdx.x * 1024 + threadIdx.x;
    if (n < NN)
        g_cursor[n] = g_incl[n] - g_deg[n] + g_bpre[blockIdx.x];
}

// ---------------- scatter: edge id + src + dst into dst-grouped order ----------------
__global__ void k_scatter(const int* __restrict__ dst, const int* __restrict__ src) {
    int e = blockIdx.x * blockDim.x + threadIdx.x;
    if (e < EE) {
        int d = dst[e];
        int s = src[e];
        int p = atomicAdd(&g_cursor[d], 1);
        g_eperm[p] = e;
        g_esrc[p] = s;
        g_edst[p] = d;
    }
}

// ---------------- node GEMM: round-4 proven version (4 nodes/warp, f32x2) ----------------
__global__ void __launch_bounds__(256) k_node(const float* __restrict__ nfeat,
                       const float* __restrict__ b_ne,
                       const float* __restrict__ b_self,
                       float* __restrict__ out_self) {
    int warp = (blockIdx.x * blockDim.x + threadIdx.x) >> 5;
    int lane = threadIdx.x & 31;
    int n0 = warp * 4;
    if (n0 >= NN) return;

    float xv[4][4];
    #pragma unroll
    for (int nk = 0; nk < 4; nk++)
        #pragma unroll
        for (int ch = 0; ch < 4; ch++)
            xv[nk][ch] = nfeat[(size_t)(n0 + nk) * 128 + ch * 32 + lane];

    int j4 = lane * 4;
    u64 ah[4][2], as[4][2];
    #pragma unroll
    for (int nk = 0; nk < 4; nk++) {
        ah[nk][0] = 0ull; ah[nk][1] = 0ull;
        as[nk][0] = 0ull; as[nk][1] = 0ull;
    }

    const u64* W1p = (const u64*)g_W1T;
    const u64* Wsp = (const u64*)g_WsT;

    #pragma unroll
    for (int ch = 0; ch < 4; ch++) {
        #pragma unroll
        for (int c = 0; c < 32; c++) {
            int k = ch * 32 + c;
            u64 w1a = W1p[k * 64 + lane * 2];
            u64 w1b = W1p[k * 64 + lane * 2 + 1];
            u64 wsa = Wsp[k * 64 + lane * 2];
            u64 wsb = Wsp[k * 64 + lane * 2 + 1];
            #pragma unroll
            for (int nk = 0; nk < 4; nk++) {
                float xk = __shfl_sync(0xffffffffu, xv[nk][ch], c);
                u64 x2 = pk2(xk, xk);
                fma2(ah[nk][0], w1a, x2);
                fma2(ah[nk][1], w1b, x2);
                fma2(as[nk][0], wsa, x2);
                fma2(as[nk][1], wsb, x2);
            }
        }
    }
    float4 bh = *(const float4*)&b_ne[j4];
    float4 bs = *(const float4*)&b_self[j4];
    #pragma unroll
    for (int nk = 0; nk < 4; nk++) {
        float2 a0 = up2(ah[nk][0]), a1 = up2(ah[nk][1]);
        float2 s0 = up2(as[nk][0]), s1 = up2(as[nk][1]);
        float4 a = make_float4(a0.x + bh.x, a0.y + bh.y, a1.x + bh.z, a1.y + bh.w);
        float4 b = make_float4(s0.x + bs.x, s0.y + bs.y, s1.x + bs.z, s1.y + bs.w);
        *(float4*)&g_h1[(size_t)(n0 + nk) * 128 + j4] = a;
        *(float4*)&out_self[(size_t)(n0 + nk) * 128 + j4] = b;
    }
}

// ---------------- edge kernel: tf32 mma, 128 edges/block ----------------
// SMEM layout (floats):
//   sEt  [128][36]    etype tile, tf32 bits          (4608)
//   sBf  [2048*2]     prepacked B frags              (4096)
//   sM   [128][132]   eh result staging              (16896)
//   sSrc [128], sDst [128]                           (256)
#define SM_ET 0
#define SM_BF (128 * 36)
#define SM_M  (SM_BF + 4096)
#define SM_SRC (SM_M + 128 * 132)
#define SM_DST (SM_SRC + 128)
#define SM_FLOATS (SM_DST + 128)      // 25856 floats = 103424 bytes

__global__ void __launch_bounds__(256) k_edge(const float* __restrict__ etype) {
    extern __shared__ float sm[];
    unsigned* sEt = (unsigned*)sm;
    unsigned* sBf = (unsigned*)(sm + SM_BF);
    float* sM = sm + SM_M;
    int* sSrc = (int*)(sm + SM_SRC);
    int* sDst = (int*)(sm + SM_DST);

    int t = threadIdx.x;
    int base = blockIdx.x * 128;   // 6250 blocks * 128 = EE exact

    if (t < 128) {
        sSrc[t] = g_esrc[base + t];
        sDst[t] = g_edst[base + t];
    }
    // stage etype rows (tf32-rounded): thread -> (row, 16-col half)
    {
        int r = t >> 1, cb = (t & 1) * 16;
        int e = g_eperm[base + r];
        const float4* p = (const float4*)(etype + (size_t)e * 32 + cb);
        float4 v0 = p[0], v1 = p[1], v2 = p[2], v3 = p[3];
        unsigned* dr = sEt + r * 36 + cb;
        dr[0]  = tf32r(v0.x); dr[1]  = tf32r(v0.y); dr[2]  = tf32r(v0.z); dr[3]  = tf32r(v0.w);
        dr[4]  = tf32r(v1.x); dr[5]  = tf32r(v1.y); dr[6]  = tf32r(v1.z); dr[7]  = tf32r(v1.w);
        dr[8]  = tf32r(v2.x); dr[9]  = tf32r(v2.y); dr[10] = tf32r(v2.z); dr[11] = tf32r(v2.w);
        dr[12] = tf32r(v3.x); dr[13] = tf32r(v3.y); dr[14] = tf32r(v3.z); dr[15] = tf32r(v3.w);
    }
    // prepack B frags (same for all warps): slot = (nt*4+ks)*32 + lane
    for (int slot = t; slot < 2048; slot += 256) {
        int lane = slot & 31, ks = (slot >> 5) & 3, nt = slot >> 7;
        int tid4 = lane & 3, g = lane >> 2;
        int k0 = ks * 8 + tid4, j = nt * 8 + g;
        sBf[slot * 2]     = __float_as_uint(g_WcT[k0 * 128 + j]);         // b0 (already tf32)
        sBf[slot * 2 + 1] = __float_as_uint(g_WcT[(k0 + 4) * 128 + j]);   // b1
    }
    __syncthreads();

    // ---- MMA phase: warp w owns edge rows [w*16, w*16+16) ----
    {
        int lane = t & 31, w = t >> 5;
        int tid4 = lane & 3, g = lane >> 2;
        int m0 = w * 16;
        unsigned a[4][4];
        #pragma unroll
        for (int ks = 0; ks < 4; ks++) {
            int k0 = ks * 8;
            a[ks][0] = sEt[(m0 + g) * 36 + k0 + tid4];
            a[ks][1] = sEt[(m0 + g + 8) * 36 + k0 + tid4];
            a[ks][2] = sEt[(m0 + g) * 36 + k0 + tid4 + 4];
            a[ks][3] = sEt[(m0 + g + 8) * 36 + k0 + tid4 + 4];
        }
        #pragma unroll
        for (int nt = 0; nt < 16; nt++) {
            float c0 = 0.f, c1 = 0.f, c2 = 0.f, c3 = 0.f;
            #pragma unroll
            for (int ks = 0; ks < 4; ks++) {
                uint2 bb = *(const uint2*)(sBf + ((nt * 4 + ks) * 32 + lane) * 2);
                mma_tf32(c0, c1, c2, c3, a[ks][0], a[ks][1], a[ks][2], a[ks][3], bb.x, bb.y);
            }
            float2* d0 = (float2*)&sM[(m0 + g) * 132 + nt * 8 + 2 * tid4];
            float2* d1 = (float2*)&sM[(m0 + g + 8) * 132 + nt * 8 + 2 * tid4];
            *d0 = make_float2(c0, c1);
            *d1 = make_float2(c2, c3);
        }
    }
    __syncthreads();

    // ---- epilogue: thread owns dim j = t>>1, rows half (t&1)*64..+64 ----
    // running segmented max over CSR-ordered rows; flush to atomicMax at dst changes.
    // cur starts 0 (absorbs relu); int atomicMax exact for non-negative floats.
    {
        int j = t >> 1;
        int r0 = (t & 1) * 64;
        float cur = 0.f;
        int dprev = sDst[r0];
        #pragma unroll 4
        for (int r = r0; r < r0 + 64; r++) {
            int d = sDst[r];
            float v = sM[r * 132 + j] + g_h1[(size_t)sSrc[r] * 128 + j];
            if (d != dprev) {
                atomicMax(&g_neigh[(size_t)dprev * 128 + j], __float_as_int(cur));
                cur = 0.f;
                dprev = d;
            }
            cur = fmaxf(cur, v);
        }
        atomicMax(&g_neigh[(size_t)dprev * 128 + j], __float_as_int(cur));
    }
}

// ---------------- final: out = self + (1+eps)*neigh ----------------
__global__ void k_final(const float* __restrict__ eps, float* __restrict__ out) {
    float s = 1.0f + eps[0];
    int idx = blockIdx.x * blockDim.x + threadIdx.x;  // NN*128/4
    float4 o = ((float4*)out)[idx];
    int4 nb = ((const int4*)g_neigh)[idx];
    o.x = fmaf(s, __int_as_float(nb.x), o.x);
    o.y = fmaf(s, __int_as_float(nb.y), o.y);
    o.z = fmaf(s, __int_as_float(nb.z), o.z);
    o.w = fmaf(s, __int_as_float(nb.w), o.w);
    ((float4*)out)[idx] = o;
}

extern "C" void kernel_launch(void* const* d_in, const int* in_sizes, int n_in,
                              void* d_out, int out_size) {
    const float* nfeat  = (const float*)d_in[0];
    const float* etype  = (const float*)d_in[1];
    const int*   src    = (const int*)d_in[2];
    const int*   dst    = (const int*)d_in[3];
    const float* W_edge = (const float*)d_in[4];
    const float* W_ne   = (const float*)d_in[5];
    const float* b_ne   = (const float*)d_in[6];
    const float* W_self = (const float*)d_in[7];
    const float* b_self = (const float*)d_in[8];
    const float* eps    = (const float*)d_in[9];
    float* out = (float*)d_out;

    static bool attr_set = false;
    if (!attr_set) {
        cudaFuncSetAttribute(k_edge, cudaFuncAttributeMaxDynamicSharedMemorySize,
                             SM_FLOATS * sizeof(float));
        attr_set = true;
    }

    k_wc<<<32, 128>>>(W_ne, W_edge);
    k_prep<<<64, 256>>>(W_ne, W_self);
    k_zero<<<(NN * 128 / 4) / 256, 256>>>();
    k_count<<<(EE + 255) / 256, 256>>>(dst);
    k_scanA<<<SCAN_BLOCKS, 1024>>>();
    k_scanB<<<1, 64>>>();
    k_scanC<<<SCAN_BLOCKS, 1024>>>();
    k_scatter<<<(EE + 255) / 256, 256>>>(dst, src);
    k_node<<<(NN / 4 + 7) / 8, 256>>>(nfeat, b_ne, b_self, out);
    k_edge<<<EE / 128, 256, SM_FLOATS * sizeof(float)>>>(etype);
    k_final<<<(NN * 128 / 4) / 256, 256>>>(eps, out);
}

// round 7
// speedup vs baseline: 1.2795x; 1.2169x over previous
#include <cuda_runtime.h>
#include <cstdint>

#define NN 50000
#define EE 800000
#define SCAN_BLOCKS 49

typedef unsigned long long u64;

// Scratch (device globals; no dynamic allocation allowed)
__device__ float g_h1[(size_t)NN * 128];   // W1 @ nfeat + b_ne per node (exact fp32)
__device__ float g_WcT[32 * 128];          // (W2 @ W_edge)T, tf32-rounded: [c][j]
__device__ uint2 g_WcF[2048];              // prepacked B frags: slot=(nt*4+ks)*32+lane
__device__ float g_W1T[128 * 128];         // W1T: [k][j]
__device__ float g_WsT[128 * 128];         // W_selfT: [k][j]
__device__ int   g_deg[NN];
__device__ int   g_incl[NN];
__device__ int   g_cursor[NN];
__device__ int   g_bsum[64];
__device__ int   g_bpre[64];
__device__ int   g_eperm[EE];              // edge ids grouped by dst
__device__ int   g_esrc[EE];               // src ids grouped by dst
__device__ int   g_edst[EE];               // dst ids grouped by dst (non-decreasing)
__device__ int   g_neigh[(size_t)NN * 128]; // float bits, atomicMax accumulator

// ---------------- helpers ----------------
__device__ __forceinline__ u64 pk2(float a, float b) {
    u64 r; asm("mov.b64 %0, {%1, %2};" : "=l"(r) : "f"(a), "f"(b)); return r;
}
__device__ __forceinline__ void fma2(u64& d, u64 a, u64 b) {
    asm("fma.rn.f32x2 %0, %1, %2, %0;" : "+l"(d) : "l"(a), "l"(b));
}
__device__ __forceinline__ float2 up2(u64 v) {
    float2 f; asm("mov.b64 {%0, %1}, %2;" : "=f"(f.x), "=f"(f.y) : "l"(v)); return f;
}
__device__ __forceinline__ unsigned tf32r(float x) {
    unsigned r; asm("cvt.rna.tf32.f32 %0, %1;" : "=r"(r) : "f"(x)); return r;
}
__device__ __forceinline__ void mma_tf32(float& c0, float& c1, float& c2, float& c3,
                                         unsigned a0, unsigned a1, unsigned a2, unsigned a3,
                                         unsigned b0, unsigned b1) {
    asm("mma.sync.aligned.m16n8k8.row.col.f32.tf32.tf32.f32 "
        "{%0,%1,%2,%3}, {%4,%5,%6,%7}, {%8,%9}, {%0,%1,%2,%3};"
        : "+f"(c0), "+f"(c1), "+f"(c2), "+f"(c3)
        : "r"(a0), "r"(a1), "r"(a2), "r"(a3), "r"(b0), "r"(b1));
}

// ---------------- prep: Wc = W2 @ W_edge, transposed, tf32-rounded ----------------
__global__ void k_wc(const float* __restrict__ W_ne, const float* __restrict__ W_edge) {
    int c = blockIdx.x;    // 0..31
    int o = threadIdx.x;   // 0..127
    float s = 0.f;
    #pragma unroll 8
    for (int j = 0; j < 128; j++)
        s += W_ne[o * 256 + 128 + j] * W_edge[j * 32 + c];
    g_WcT[c * 128 + o] = __uint_as_float(tf32r(s));
}

// ---------------- prep: pack B fragments once (runs after k_wc) ----------------
__global__ void k_wpack() {
    int slot = blockIdx.x * 256 + threadIdx.x;   // 2048 slots
    int lane = slot & 31, ks = (slot >> 5) & 3, nt = slot >> 7;
    int tid4 = lane & 3, g = lane >> 2;
    int k0 = ks * 8 + tid4, j = nt * 8 + g;
    g_WcF[slot] = make_uint2(__float_as_uint(g_WcT[k0 * 128 + j]),
                             __float_as_uint(g_WcT[(k0 + 4) * 128 + j]));
}

// ---------------- prep: transpose W1 / W_self; zero deg ----------------
__global__ void k_prep(const float* __restrict__ W_ne, const float* __restrict__ W_self) {
    int idx = blockIdx.x * blockDim.x + threadIdx.x;  // 16384
    int j = idx >> 7, k = idx & 127;
    g_W1T[k * 128 + j] = W_ne[j * 256 + k];
    g_WsT[k * 128 + j] = W_self[j * 128 + k];
    for (int n = idx; n < NN; n += 16384) g_deg[n] = 0;
}

// ---------------- zero the neigh accumulator ----------------
__global__ void k_zero() {
    int idx = blockIdx.x * blockDim.x + threadIdx.x;  // NN*128/4
    int4 z = {0, 0, 0, 0};
    ((int4*)g_neigh)[idx] = z;
}

// ---------------- degree count ----------------
__global__ void k_count(const int* __restrict__ dst) {
    int e = blockIdx.x * blockDim.x + threadIdx.x;
    if (e < EE) atomicAdd(&g_deg[dst[e]], 1);
}

// ---------------- scan A ----------------
__global__ void k_scanA() {
    int n = blockIdx.x * 1024 + threadIdx.x;
    int lane = threadIdx.x & 31, w = threadIdx.x >> 5;
    int v = (n < NN) ? g_deg[n] : 0;
    int x = v;
    #pragma unroll
    for (int d = 1; d < 32; d <<= 1) {
        int y = __shfl_up_sync(0xffffffffu, x, d);
        if (lane >= d) x += y;
    }
    __shared__ int ws[32];
    if (lane == 31) ws[w] = x;
    __syncthreads();
    if (w == 0) {
        int y = ws[lane];
        #pragma unroll
        for (int d = 1; d < 32; d <<= 1) {
            int z = __shfl_up_sync(0xffffffffu, y, d);
            if (lane >= d) y += z;
        }
        ws[lane] = y;
    }
    __syncthreads();
    int incl = x + ((w > 0) ? ws[w - 1] : 0);
    if (n < NN) g_incl[n] = incl;
    if (threadIdx.x == 1023) g_bsum[blockIdx.x] = incl;
}

// ---------------- scan B ----------------
__global__ void k_scanB() {
    __shared__ int s[64];
    int t = threadIdx.x;
    int v = (t < SCAN_BLOCKS) ? g_bsum[t] : 0;
    s[t] = v;
    __syncthreads();
    for (int d = 1; d < 64; d <<= 1) {
        int y = (t >= d) ? s[t - d] : 0;
        __syncthreads();
        s[t] += y;
        __syncthreads();
    }
    if (t < SCAN_BLOCKS) g_bpre[t] = s[t] - v;
}

// ---------------- scan C: cursors ----------------
__global__ void k_scanC() {
    int n = blockIdx.x * 1024 + threadIdx.x;
    if (n < NN)
        g_cursor[n] = g_incl[n] - g_deg[n] + g_bpre[blockIdx.x];
}

// ---------------- scatter: edge id + src + dst into dst-grouped order ----------------
__global__ void k_scatter(const int* __restrict__ dst, const int* __restrict__ src) {
    int e = blockIdx.x * blockDim.x + threadIdx.x;
    if (e < EE) {
        int d = dst[e];
        int s = src[e];
        int p = atomicAdd(&g_cursor[d], 1);
        g_eperm[p] = e;
        g_esrc[p] = s;
        g_edst[p] = d;
    }
}

// ---------------- node GEMM: round-4 proven version (4 nodes/warp, f32x2) ----------------
__global__ void __launch_bounds__(256) k_node(const float* __restrict__ nfeat,
                       const float* __restrict__ b_ne,
                       const float* __restrict__ b_self,
                       float* __restrict__ out_self) {
    int warp = (blockIdx.x * blockDim.x + threadIdx.x) >> 5;
    int lane = threadIdx.x & 31;
    int n0 = warp * 4;
    if (n0 >= NN) return;

    float xv[4][4];
    #pragma unroll
    for (int nk = 0; nk < 4; nk++)
        #pragma unroll
        for (int ch = 0; ch < 4; ch++)
            xv[nk][ch] = nfeat[(size_t)(n0 + nk) * 128 + ch * 32 + lane];

    int j4 = lane * 4;
    u64 ah[4][2], as[4][2];
    #pragma unroll
    for (int nk = 0; nk < 4; nk++) {
        ah[nk][0] = 0ull; ah[nk][1] = 0ull;
        as[nk][0] = 0ull; as[nk][1] = 0ull;
    }

    const u64* W1p = (const u64*)g_W1T;
    const u64* Wsp = (const u64*)g_WsT;

    #pragma unroll
    for (int ch = 0; ch < 4; ch++) {
        #pragma unroll
        for (int c = 0; c < 32; c++) {
            int k = ch * 32 + c;
            u64 w1a = W1p[k * 64 + lane * 2];
            u64 w1b = W1p[k * 64 + lane * 2 + 1];
            u64 wsa = Wsp[k * 64 + lane * 2];
            u64 wsb = Wsp[k * 64 + lane * 2 + 1];
            #pragma unroll
            for (int nk = 0; nk < 4; nk++) {
                float xk = __shfl_sync(0xffffffffu, xv[nk][ch], c);
                u64 x2 = pk2(xk, xk);
                fma2(ah[nk][0], w1a, x2);
                fma2(ah[nk][1], w1b, x2);
                fma2(as[nk][0], wsa, x2);
                fma2(as[nk][1], wsb, x2);
            }
        }
    }
    float4 bh = *(const float4*)&b_ne[j4];
    float4 bs = *(const float4*)&b_self[j4];
    #pragma unroll
    for (int nk = 0; nk < 4; nk++) {
        float2 a0 = up2(ah[nk][0]), a1 = up2(ah[nk][1]);
        float2 s0 = up2(as[nk][0]), s1 = up2(as[nk][1]);
        float4 a = make_float4(a0.x + bh.x, a0.y + bh.y, a1.x + bh.z, a1.y + bh.w);
        float4 b = make_float4(s0.x + bs.x, s0.y + bs.y, s1.x + bs.z, s1.y + bs.w);
        *(float4*)&g_h1[(size_t)(n0 + nk) * 128 + j4] = a;
        *(float4*)&out_self[(size_t)(n0 + nk) * 128 + j4] = b;
    }
}

// ---------------- edge kernel: tf32 mma, 64 edges/block, 128 threads, static smem ----------------
__global__ void __launch_bounds__(128) k_edge(const float* __restrict__ etype) {
    __shared__ unsigned sEt[64 * 36];   // etype tile, tf32 bits (9216 B)
    __shared__ float sM[64 * 132];      // eh staging (33792 B)
    __shared__ int sSrc[64];
    __shared__ int sDst[64];

    int t = threadIdx.x;
    int base = blockIdx.x * 64;   // 12500 blocks * 64 = EE exact

    if (t < 64) {
        sSrc[t] = g_esrc[base + t];
        sDst[t] = g_edst[base + t];
    }
    // stage etype rows (tf32-rounded): thread -> (row = t>>1, 16-col half)
    {
        int r = t >> 1, cb = (t & 1) * 16;
        int e = g_eperm[base + r];
        const float4* p = (const float4*)(etype + (size_t)e * 32 + cb);
        float4 v0 = p[0], v1 = p[1], v2 = p[2], v3 = p[3];
        unsigned* dr = sEt + r * 36 + cb;
        dr[0]  = tf32r(v0.x); dr[1]  = tf32r(v0.y); dr[2]  = tf32r(v0.z); dr[3]  = tf32r(v0.w);
        dr[4]  = tf32r(v1.x); dr[5]  = tf32r(v1.y); dr[6]  = tf32r(v1.z); dr[7]  = tf32r(v1.w);
        dr[8]  = tf32r(v2.x); dr[9]  = tf32r(v2.y); dr[10] = tf32r(v2.z); dr[11] = tf32r(v2.w);
        dr[12] = tf32r(v3.x); dr[13] = tf32r(v3.y); dr[14] = tf32r(v3.z); dr[15] = tf32r(v3.w);
    }
    __syncthreads();

    // ---- MMA phase: warp w (0..3) owns edge rows [w*16, w*16+16) ----
    {
        int lane = t & 31, w = t >> 5;
        int tid4 = lane & 3, g = lane >> 2;
        int m0 = w * 16;
        unsigned a[4][4];
        #pragma unroll
        for (int ks = 0; ks < 4; ks++) {
            int k0 = ks * 8;
            a[ks][0] = sEt[(m0 + g) * 36 + k0 + tid4];
            a[ks][1] = sEt[(m0 + g + 8) * 36 + k0 + tid4];
            a[ks][2] = sEt[(m0 + g) * 36 + k0 + tid4 + 4];
            a[ks][3] = sEt[(m0 + g + 8) * 36 + k0 + tid4 + 4];
        }
        #pragma unroll
        for (int nt = 0; nt < 16; nt++) {
            float c0 = 0.f, c1 = 0.f, c2 = 0.f, c3 = 0.f;
            #pragma unroll
            for (int ks = 0; ks < 4; ks++) {
                uint2 bb = g_WcF[(nt * 4 + ks) * 32 + lane];   // coalesced, L1-resident
                mma_tf32(c0, c1, c2, c3, a[ks][0], a[ks][1], a[ks][2], a[ks][3], bb.x, bb.y);
            }
            *(float2*)&sM[(m0 + g) * 132 + nt * 8 + 2 * tid4]     = make_float2(c0, c1);
            *(float2*)&sM[(m0 + g + 8) * 132 + nt * 8 + 2 * tid4] = make_float2(c2, c3);
        }
    }
    __syncthreads();

    // ---- epilogue: thread t owns column j=t; scan 64 CSR-ordered rows ----
    // h1 row load is a block-wide broadcast (coalesced 512B); segmented max,
    // flush via atomicMax at dst changes. cur=0 absorbs relu; int-max exact for >=0.
    {
        int j = t;
        float cur = 0.f;
        int dprev = sDst[0];
        #pragma unroll 4
        for (int r = 0; r < 64; r++) {
            int d = sDst[r];
            float v = sM[r * 132 + j] + g_h1[(size_t)sSrc[r] * 128 + j];
            if (d != dprev) {
                atomicMax(&g_neigh[(size_t)dprev * 128 + j], __float_as_int(cur));
                cur = 0.f;
                dprev = d;
            }
            cur = fmaxf(cur, v);
        }
        atomicMax(&g_neigh[(size_t)dprev * 128 + j], __float_as_int(cur));
    }
}

// ---------------- final: out = self + (1+eps)*neigh ----------------
__global__ void k_final(const float* __restrict__ eps, float* __restrict__ out) {
    float s = 1.0f + eps[0];
    int idx = blockIdx.x * blockDim.x + threadIdx.x;  // NN*128/4
    float4 o = ((float4*)out)[idx];
    int4 nb = ((const int4*)g_neigh)[idx];
    o.x = fmaf(s, __int_as_float(nb.x), o.x);
    o.y = fmaf(s, __int_as_float(nb.y), o.y);
    o.z = fmaf(s, __int_as_float(nb.z), o.z);
    o.w = fmaf(s, __int_as_float(nb.w), o.w);
    ((float4*)out)[idx] = o;
}

extern "C" void kernel_launch(void* const* d_in, const int* in_sizes, int n_in,
                              void* d_out, int out_size) {
    const float* nfeat  = (const float*)d_in[0];
    const float* etype  = (const float*)d_in[1];
    const int*   src    = (const int*)d_in[2];
    const int*   dst    = (const int*)d_in[3];
    const float* W_edge = (const float*)d_in[4];
    const float* W_ne   = (const float*)d_in[5];
    const float* b_ne   = (const float*)d_in[6];
    const float* W_self = (const float*)d_in[7];
    const float* b_self = (const float*)d_in[8];
    const float* eps    = (const float*)d_in[9];
    float* out = (float*)d_out;

    k_wc<<<32, 128>>>(W_ne, W_edge);
    k_wpack<<<8, 256>>>();
    k_prep<<<64, 256>>>(W_ne, W_self);
    k_zero<<<(NN * 128 / 4) / 256, 256>>>();
    k_count<<<(EE + 255) / 256, 256>>>(dst);
    k_scanA<<<SCAN_BLOCKS, 1024>>>();
    k_scanB<<<1, 64>>>();
    k_scanC<<<SCAN_BLOCKS, 1024>>>();
    k_scatter<<<(EE + 255) / 256, 256>>>(dst, src);
    k_node<<<(NN / 4 + 7) / 8, 256>>>(nfeat, b_ne, b_self, out);
    k_edge<<<EE / 64, 128>>>(etype);
    k_final<<<(NN * 128 / 4) / 256, 256>>>(eps, out);
}

// round 8
// speedup vs baseline: 1.5866x; 1.2400x over previous
#include <cuda_runtime.h>
#include <cstdint>

#define NN 50000
#define EE 800000
#define SCAN_BLOCKS 49

// Scratch (device globals; no dynamic allocation allowed)
__device__ float g_h1[(size_t)NN * 128];   // W1 @ nfeat + b_ne per node (tf32 MMA)
__device__ float g_WcT[32 * 128];          // (W2 @ W_edge)T, tf32-rounded: [c][j]
__device__ uint2 g_WcF[2048];              // prepacked edge-B frags
__device__ uint2 g_WnF[16384];             // prepacked node-B frags: [W1 | W_self], 256 cols
__device__ int   g_deg[NN];
__device__ int   g_incl[NN];
__device__ int   g_cursor[NN];
__device__ int   g_bsum[64];
__device__ int   g_bpre[64];
__device__ int   g_eperm[EE];              // edge ids grouped by dst
__device__ int   g_esrc[EE];               // src ids grouped by dst
__device__ int   g_edst[EE];               // dst ids grouped by dst (non-decreasing)
__device__ int   g_neigh[(size_t)NN * 128]; // float bits, atomicMax accumulator

// ---------------- helpers ----------------
__device__ __forceinline__ unsigned tf32r(float x) {
    unsigned r; asm("cvt.rna.tf32.f32 %0, %1;" : "=r"(r) : "f"(x)); return r;
}
__device__ __forceinline__ void mma_tf32(float& c0, float& c1, float& c2, float& c3,
                                         unsigned a0, unsigned a1, unsigned a2, unsigned a3,
                                         unsigned b0, unsigned b1) {
    asm("mma.sync.aligned.m16n8k8.row.col.f32.tf32.tf32.f32 "
        "{%0,%1,%2,%3}, {%4,%5,%6,%7}, {%8,%9}, {%0,%1,%2,%3};"
        : "+f"(c0), "+f"(c1), "+f"(c2), "+f"(c3)
        : "r"(a0), "r"(a1), "r"(a2), "r"(a3), "r"(b0), "r"(b1));
}

// ---------------- prep: Wc = W2 @ W_edge, transposed, tf32-rounded ----------------
__global__ void k_wc(const float* __restrict__ W_ne, const float* __restrict__ W_edge) {
    int c = blockIdx.x;    // 0..31
    int o = threadIdx.x;   // 0..127
    float s = 0.f;
    #pragma unroll 8
    for (int j = 0; j < 128; j++)
        s += W_ne[o * 256 + 128 + j] * W_edge[j * 32 + c];
    g_WcT[c * 128 + o] = __uint_as_float(tf32r(s));
}

// ---------------- prep: pack edge-B fragments ----------------
__global__ void k_wpack() {
    int slot = blockIdx.x * 256 + threadIdx.x;   // 2048 slots
    int lane = slot & 31, ks = (slot >> 5) & 3, nt = slot >> 7;
    int tid4 = lane & 3, g = lane >> 2;
    int k0 = ks * 8 + tid4, j = nt * 8 + g;
    g_WcF[slot] = make_uint2(__float_as_uint(g_WcT[k0 * 128 + j]),
                             __float_as_uint(g_WcT[(k0 + 4) * 128 + j]));
}

// ---------------- prep: pack node-B frags ([W1 | W_self] tf32), zero deg ----------------
// B[k][j] = (j<128) ? W_ne[j*256+k] : W_self[(j-128)*128+k]
__global__ void k_prep(const float* __restrict__ W_ne, const float* __restrict__ W_self) {
    int slot = blockIdx.x * 256 + threadIdx.x;   // 16384 slots
    int lane = slot & 31, ks = (slot >> 5) & 15, nt = slot >> 9;  // nt 0..31
    int tid4 = lane & 3, g = lane >> 2;
    int k0 = ks * 8 + tid4, j = nt * 8 + g;
    float b0, b1;
    if (j < 128) {
        b0 = W_ne[j * 256 + k0];
        b1 = W_ne[j * 256 + k0 + 4];
    } else {
        b0 = W_self[(j - 128) * 128 + k0];
        b1 = W_self[(j - 128) * 128 + k0 + 4];
    }
    g_WnF[slot] = make_uint2(tf32r(b0), tf32r(b1));
    for (int n = slot; n < NN; n += 16384) g_deg[n] = 0;
}

// ---------------- zero the neigh accumulator ----------------
__global__ void k_zero() {
    int idx = blockIdx.x * blockDim.x + threadIdx.x;  // NN*128/4
    int4 z = {0, 0, 0, 0};
    ((int4*)g_neigh)[idx] = z;
}

// ---------------- degree count ----------------
__global__ void k_count(const int* __restrict__ dst) {
    int e = blockIdx.x * blockDim.x + threadIdx.x;
    if (e < EE) atomicAdd(&g_deg[dst[e]], 1);
}

// ---------------- scan A ----------------
__global__ void k_scanA() {
    int n = blockIdx.x * 1024 + threadIdx.x;
    int lane = threadIdx.x & 31, w = threadIdx.x >> 5;
    int v = (n < NN) ? g_deg[n] : 0;
    int x = v;
    #pragma unroll
    for (int d = 1; d < 32; d <<= 1) {
        int y = __shfl_up_sync(0xffffffffu, x, d);
        if (lane >= d) x += y;
    }
    __shared__ int ws[32];
    if (lane == 31) ws[w] = x;
    __syncthreads();
    if (w == 0) {
        int y = ws[lane];
        #pragma unroll
        for (int d = 1; d < 32; d <<= 1) {
            int z = __shfl_up_sync(0xffffffffu, y, d);
            if (lane >= d) y += z;
        }
        ws[lane] = y;
    }
    __syncthreads();
    int incl = x + ((w > 0) ? ws[w - 1] : 0);
    if (n < NN) g_incl[n] = incl;
    if (threadIdx.x == 1023) g_bsum[blockIdx.x] = incl;
}

// ---------------- scan B ----------------
__global__ void k_scanB() {
    __shared__ int s[64];
    int t = threadIdx.x;
    int v = (t < SCAN_BLOCKS) ? g_bsum[t] : 0;
    s[t] = v;
    __syncthreads();
    for (int d = 1; d < 64; d <<= 1) {
        int y = (t >= d) ? s[t - d] : 0;
        __syncthreads();
        s[t] += y;
        __syncthreads();
    }
    if (t < SCAN_BLOCKS) g_bpre[t] = s[t] - v;
}

// ---------------- scan C: cursors ----------------
__global__ void k_scanC() {
    int n = blockIdx.x * 1024 + threadIdx.x;
    if (n < NN)
        g_cursor[n] = g_incl[n] - g_deg[n] + g_bpre[blockIdx.x];
}

// ---------------- scatter ----------------
__global__ void k_scatter(const int* __restrict__ dst, const int* __restrict__ src) {
    int e = blockIdx.x * blockDim.x + threadIdx.x;
    if (e < EE) {
        int d = dst[e];
        int s = src[e];
        int p = atomicAdd(&g_cursor[d], 1);
        g_eperm[p] = e;
        g_esrc[p] = s;
        g_edst[p] = d;
    }
}

// ---------------- node GEMM: tf32 mma, 32 nodes/block, fused [h1 | self] ----------------
__global__ void __launch_bounds__(128) k_node(const float* __restrict__ nfeat,
                       const float* __restrict__ b_ne,
                       const float* __restrict__ b_self,
                       float* __restrict__ out) {
    __shared__ unsigned sA[32 * 132];   // 32 nodes x 128 k, tf32 bits
    __shared__ float sB[256];           // [b_ne | b_self]

    int t = threadIdx.x;
    int base = blockIdx.x * 32;   // 1563 blocks; last covers 16 valid nodes

    // stage A: row r = t>>2, k-quarter cb = (t&3)*32
    {
        int r = t >> 2, cb = (t & 3) * 32;
        int node = base + r; if (node >= NN) node = NN - 1;   // clamp (tail)
        const float4* p = (const float4*)(nfeat + (size_t)node * 128 + cb);
        unsigned* dr = sA + r * 132 + cb;
        #pragma unroll
        for (int i = 0; i < 8; i++) {
            float4 v = p[i];
            dr[i * 4 + 0] = tf32r(v.x); dr[i * 4 + 1] = tf32r(v.y);
            dr[i * 4 + 2] = tf32r(v.z); dr[i * 4 + 3] = tf32r(v.w);
        }
    }
    if (t < 128) { sB[t] = b_ne[t]; sB[128 + t] = b_self[t]; }
    __syncthreads();

    int lane = t & 31, w = t >> 5;
    int tid4 = lane & 3, g = lane >> 2;
    int m0 = (w >> 1) * 16;       // rows 0 or 16
    int ntb = (w & 1) * 16;       // col-tile base: 0 => h1 cols, 16 => self cols

    float acc[16][4];
    #pragma unroll
    for (int nt = 0; nt < 16; nt++)
        #pragma unroll
        for (int i = 0; i < 4; i++) acc[nt][i] = 0.f;

    #pragma unroll
    for (int ks = 0; ks < 16; ks++) {
        int k0 = ks * 8;
        unsigned a0 = sA[(m0 + g) * 132 + k0 + tid4];
        unsigned a1 = sA[(m0 + g + 8) * 132 + k0 + tid4];
        unsigned a2 = sA[(m0 + g) * 132 + k0 + tid4 + 4];
        unsigned a3 = sA[(m0 + g + 8) * 132 + k0 + tid4 + 4];
        #pragma unroll
        for (int nt = 0; nt < 16; nt++) {
            uint2 bb = g_WnF[((ntb + nt) * 16 + ks) * 32 + lane];
            mma_tf32(acc[nt][0], acc[nt][1], acc[nt][2], acc[nt][3], a0, a1, a2, a3, bb.x, bb.y);
        }
    }

    // epilogue: bias + store. warp's cols are all-h1 (ntb=0) or all-self (ntb=16).
    int na = base + m0 + g, nb = na + 8;
    bool va = (na < NN), vb = (nb < NN);
    float* dsta = (ntb == 0) ? g_h1 : out;
    int jo = (ntb == 0) ? 0 : 128;
    #pragma unroll
    for (int nt = 0; nt < 16; nt++) {
        int jc = (ntb + nt) * 8 + 2 * tid4;       // global col in [0,256)
        float bx = sB[jc], by = sB[jc + 1];
        if (va) *(float2*)&dsta[(size_t)na * 128 + (jc - jo)] =
            make_float2(acc[nt][0] + bx, acc[nt][1] + by);
        if (vb) *(float2*)&dsta[(size_t)nb * 128 + (jc - jo)] =
            make_float2(acc[nt][2] + bx, acc[nt][3] + by);
    }
}

// ---------------- edge kernel: tf32 mma, 64 edges/block (round-7 proven) ----------------
__global__ void __launch_bounds__(128) k_edge(const float* __restrict__ etype) {
    __shared__ unsigned sEt[64 * 36];
    __shared__ float sM[64 * 132];
    __shared__ int sSrc[64];
    __shared__ int sDst[64];

    int t = threadIdx.x;
    int base = blockIdx.x * 64;   // 12500 blocks

    if (t < 64) {
        sSrc[t] = g_esrc[base + t];
        sDst[t] = g_edst[base + t];
    }
    {
        int r = t >> 1, cb = (t & 1) * 16;
        int e = g_eperm[base + r];
        const float4* p = (const float4*)(etype + (size_t)e * 32 + cb);
        float4 v0 = p[0], v1 = p[1], v2 = p[2], v3 = p[3];
        unsigned* dr = sEt + r * 36 + cb;
        dr[0]  = tf32r(v0.x); dr[1]  = tf32r(v0.y); dr[2]  = tf32r(v0.z); dr[3]  = tf32r(v0.w);
        dr[4]  = tf32r(v1.x); dr[5]  = tf32r(v1.y); dr[6]  = tf32r(v1.z); dr[7]  = tf32r(v1.w);
        dr[8]  = tf32r(v2.x); dr[9]  = tf32r(v2.y); dr[10] = tf32r(v2.z); dr[11] = tf32r(v2.w);
        dr[12] = tf32r(v3.x); dr[13] = tf32r(v3.y); dr[14] = tf32r(v3.z); dr[15] = tf32r(v3.w);
    }
    __syncthreads();

    {
        int lane = t & 31, w = t >> 5;
        int tid4 = lane & 3, g = lane >> 2;
        int m0 = w * 16;
        unsigned a[4][4];
        #pragma unroll
        for (int ks = 0; ks < 4; ks++) {
            int k0 = ks * 8;
            a[ks][0] = sEt[(m0 + g) * 36 + k0 + tid4];
            a[ks][1] = sEt[(m0 + g + 8) * 36 + k0 + tid4];
            a[ks][2] = sEt[(m0 + g) * 36 + k0 + tid4 + 4];
            a[ks][3] = sEt[(m0 + g + 8) * 36 + k0 + tid4 + 4];
        }
        #pragma unroll
        for (int nt = 0; nt < 16; nt++) {
            float c0 = 0.f, c1 = 0.f, c2 = 0.f, c3 = 0.f;
            #pragma unroll
            for (int ks = 0; ks < 4; ks++) {
                uint2 bb = g_WcF[(nt * 4 + ks) * 32 + lane];
                mma_tf32(c0, c1, c2, c3, a[ks][0], a[ks][1], a[ks][2], a[ks][3], bb.x, bb.y);
            }
            *(float2*)&sM[(m0 + g) * 132 + nt * 8 + 2 * tid4]     = make_float2(c0, c1);
            *(float2*)&sM[(m0 + g + 8) * 132 + nt * 8 + 2 * tid4] = make_float2(c2, c3);
        }
    }
    __syncthreads();

    // epilogue: thread t owns column j=t; segmented max over 64 CSR-ordered rows
    {
        int j = t;
        float cur = 0.f;
        int dprev = sDst[0];
        #pragma unroll 4
        for (int r = 0; r < 64; r++) {
            int d = sDst[r];
            float v = sM[r * 132 + j] + g_h1[(size_t)sSrc[r] * 128 + j];
            if (d != dprev) {
                atomicMax(&g_neigh[(size_t)dprev * 128 + j], __float_as_int(cur));
                cur = 0.f;
                dprev = d;
            }
            cur = fmaxf(cur, v);
        }
        atomicMax(&g_neigh[(size_t)dprev * 128 + j], __float_as_int(cur));
    }
}

// ---------------- final: out = self + (1+eps)*neigh ----------------
__global__ void k_final(const float* __restrict__ eps, float* __restrict__ out) {
    float s = 1.0f + eps[0];
    int idx = blockIdx.x * blockDim.x + threadIdx.x;  // NN*128/4
    float4 o = ((float4*)out)[idx];
    int4 nb = ((const int4*)g_neigh)[idx];
    o.x = fmaf(s, __int_as_float(nb.x), o.x);
    o.y = fmaf(s, __int_as_float(nb.y), o.y);
    o.z = fmaf(s, __int_as_float(nb.z), o.z);
    o.w = fmaf(s, __int_as_float(nb.w), o.w);
    ((float4*)out)[idx] = o;
}

extern "C" void kernel_launch(void* const* d_in, const int* in_sizes, int n_in,
                              void* d_out, int out_size) {
    const float* nfeat  = (const float*)d_in[0];
    const float* etype  = (const float*)d_in[1];
    const int*   src    = (const int*)d_in[2];
    const int*   dst    = (const int*)d_in[3];
    const float* W_edge = (const float*)d_in[4];
    const float* W_ne   = (const float*)d_in[5];
    const float* b_ne   = (const float*)d_in[6];
    const float* W_self = (const float*)d_in[7];
    const float* b_self = (const float*)d_in[8];
    const float* eps    = (const float*)d_in[9];
    float* out = (float*)d_out;

    k_wc<<<32, 128>>>(W_ne, W_edge);
    k_wpack<<<8, 256>>>();
    k_prep<<<64, 256>>>(W_ne, W_self);
    k_zero<<<(NN * 128 / 4) / 256, 256>>>();
    k_count<<<(EE + 255) / 256, 256>>>(dst);
    k_scanA<<<SCAN_BLOCKS, 1024>>>();
    k_scanB<<<1, 64>>>();
    k_scanC<<<SCAN_BLOCKS, 1024>>>();
    k_scatter<<<(EE + 255) / 256, 256>>>(dst, src);
    k_node<<<(NN + 31) / 32, 128>>>(nfeat, b_ne, b_self, out);
    k_edge<<<EE / 64, 128>>>(etype);
    k_final<<<(NN * 128 / 4) / 256, 256>>>(eps, out);
}